// round 1
// baseline (speedup 1.0000x reference)
#include <cuda_runtime.h>
#include <cstdint>

#define N_NODES 50000
#define N_FEAT  128
#define N_EDGES 800000
#define ALPHA   0.2f
#define EPS     1e-16f

// ---------------- scratch (device globals; no allocation allowed) ----------
__device__ float d_Wh[N_NODES * N_FEAT];      // 25.6 MB, L2-resident
__device__ float d_s1[N_NODES];
__device__ float d_s2[N_NODES];
__device__ float d_e[N_EDGES];                // e, then overwritten with e_exp
__device__ float d_rowsum[N_NODES];
__device__ float d_expsum[N_NODES];
__device__ int   d_counts[N_NODES];
__device__ int   d_starts[N_NODES + 1];
__device__ int   d_cursor[N_NODES];
__device__ int   d_perm[N_EDGES];
__device__ int   g_is64;

// ---------------- edge-index dtype detection -------------------------------
// If the buffer holds int32 node ids, reading it as uint64 combines pairs and
// the high word is a (almost surely nonzero) node id -> values >> N_NODES.
__global__ void detect_kernel(const void* ei) {
    if (threadIdx.x == 0 && blockIdx.x == 0) {
        const unsigned long long* p = (const unsigned long long*)ei;
        int big = 0;
        for (int i = 0; i < 64; i++)
            if (p[i] > (unsigned long long)N_NODES) big++;
        g_is64 = (big < 32) ? 1 : 0;
    }
}

__device__ __forceinline__ int edge_get(const void* ei, int which, int i, int is64) {
    if (is64) return (int)((const long long*)ei)[(size_t)which * N_EDGES + i];
    return ((const int*)ei)[which * N_EDGES + i];
}

// ---------------- zero counters --------------------------------------------
__global__ void zero_kernel() {
    int idx = blockIdx.x * blockDim.x + threadIdx.x;
    int stride = gridDim.x * blockDim.x;
    for (int i = idx; i < N_NODES; i += stride) {
        d_rowsum[i] = 0.0f;
        d_expsum[i] = 0.0f;
        d_counts[i] = 0;
        d_cursor[i] = 0;
    }
}

// ---------------- GEMM: Wh = h @ W  (fp32) ---------------------------------
// Block: 256 threads, 32-row tile. Thread (cg = t&31, rg = t>>5) computes a
// 4-row x 4-col register tile. W read through L1 (64 KB, resident),
// h tile staged in static smem (16 KB).
__global__ void gemm_kernel(const float* __restrict__ h, const float* __restrict__ W) {
    __shared__ float hs[32 * N_FEAT];
    const int t = threadIdx.x;
    const int row0 = blockIdx.x * 32;

    // stage h tile (float4), zero-fill out-of-range rows
    for (int i = t; i < 32 * (N_FEAT / 4); i += 256) {
        int r = i >> 5;            // 32 float4 per row
        int c4 = i & 31;
        float4 v = make_float4(0.f, 0.f, 0.f, 0.f);
        int gr = row0 + r;
        if (gr < N_NODES) v = ((const float4*)h)[(size_t)gr * 32 + c4];
        ((float4*)hs)[i] = v;
    }
    __syncthreads();

    const int cg = t & 31;
    const int rg = t >> 5;
    float acc[4][4];
#pragma unroll
    for (int j = 0; j < 4; j++)
#pragma unroll
        for (int c = 0; c < 4; c++) acc[j][c] = 0.0f;

    const float4* Wv = (const float4*)W;   // W[k][4cg..] = Wv[k*32+cg]
#pragma unroll 4
    for (int k = 0; k < N_FEAT; k++) {
        float4 w = __ldg(&Wv[k * 32 + cg]);
#pragma unroll
        for (int j = 0; j < 4; j++) {
            float hv = hs[(rg * 4 + j) * N_FEAT + k];
            acc[j][0] += hv * w.x;
            acc[j][1] += hv * w.y;
            acc[j][2] += hv * w.z;
            acc[j][3] += hv * w.w;
        }
    }

#pragma unroll
    for (int j = 0; j < 4; j++) {
        int gr = row0 + rg * 4 + j;
        if (gr < N_NODES)
            ((float4*)d_Wh)[(size_t)gr * 32 + cg] =
                make_float4(acc[j][0], acc[j][1], acc[j][2], acc[j][3]);
    }
}

// ---------------- s1/s2 = Wh @ a1, Wh @ a2 (warp per row) ------------------
__global__ void score_kernel(const float* __restrict__ a) {
    int warp = (blockIdx.x * blockDim.x + threadIdx.x) >> 5;
    int lane = threadIdx.x & 31;
    if (warp >= N_NODES) return;
    float4 v  = ((const float4*)d_Wh)[(size_t)warp * 32 + lane];
    float4 a1 = __ldg(&((const float4*)a)[lane]);
    float4 a2 = __ldg(&((const float4*)a)[32 + lane]);
    float s1 = v.x * a1.x + v.y * a1.y + v.z * a1.z + v.w * a1.w;
    float s2 = v.x * a2.x + v.y * a2.y + v.z * a2.z + v.w * a2.w;
#pragma unroll
    for (int off = 16; off > 0; off >>= 1) {
        s1 += __shfl_down_sync(0xffffffffu, s1, off);
        s2 += __shfl_down_sync(0xffffffffu, s2, off);
    }
    if (lane == 0) { d_s1[warp] = s1; d_s2[warp] = s2; }
}

// ---------------- edge pass 1: e, rowsum, degree histogram -----------------
__global__ void edge1_kernel(const void* __restrict__ ei) {
    int i = blockIdx.x * blockDim.x + threadIdx.x;
    if (i >= N_EDGES) return;
    const int is64 = g_is64;
    int r = edge_get(ei, 0, i, is64);
    int c = edge_get(ei, 1, i, is64);
    float e = d_s1[r] + d_s2[c];
    e = (e > 0.0f) ? e : ALPHA * e;
    d_e[i] = e;
    atomicAdd(&d_rowsum[r], e);
    atomicAdd(&d_counts[r], 1);
}

// ---------------- single-block exclusive scan of counts --------------------
__global__ void scan_kernel() {
    __shared__ int sums[1024];
    const int t = threadIdx.x;
    const int CH = (N_NODES + 1023) / 1024;   // 49
    const int base = t * CH;
    int s = 0;
    for (int i = 0; i < CH; i++) {
        int idx = base + i;
        if (idx < N_NODES) s += d_counts[idx];
    }
    sums[t] = s;
    __syncthreads();
    for (int off = 1; off < 1024; off <<= 1) {
        int v = (t >= off) ? sums[t - off] : 0;
        __syncthreads();
        sums[t] += v;
        __syncthreads();
    }
    int run = (t == 0) ? 0 : sums[t - 1];
    for (int i = 0; i < CH; i++) {
        int idx = base + i;
        if (idx < N_NODES) {
            d_starts[idx] = run;
            run += d_counts[idx];
        }
    }
    if (t == 1023) d_starts[N_NODES] = sums[1023];
}

// ---------------- edge pass 2: exp, expsum, permutation scatter ------------
__global__ void edge2_kernel(const void* __restrict__ ei) {
    int i = blockIdx.x * blockDim.x + threadIdx.x;
    if (i >= N_EDGES) return;
    const int is64 = g_is64;
    int r = edge_get(ei, 0, i, is64);
    float ex = expf(d_e[i] - d_rowsum[r]);
    d_e[i] = ex;                      // reuse as e_exp
    atomicAdd(&d_expsum[r], ex);
    int pos = d_starts[r] + atomicAdd(&d_cursor[r], 1);
    d_perm[pos] = i;
}

// ---------------- aggregation: warp per node, no atomics -------------------
__global__ void agg_kernel(const void* __restrict__ ei, float* __restrict__ out) {
    int warp = (blockIdx.x * blockDim.x + threadIdx.x) >> 5;
    int lane = threadIdx.x & 31;
    if (warp >= N_NODES) return;
    const int is64 = g_is64;
    const int st = d_starts[warp];
    const int en = d_starts[warp + 1];
    const float denom = d_expsum[warp] + EPS;
    float4 acc = make_float4(0.f, 0.f, 0.f, 0.f);
    for (int p = st; p < en; p++) {
        int eid = d_perm[p];
        int c = edge_get(ei, 1, eid, is64);
        float w = d_e[eid] / denom;
        float4 v = ((const float4*)d_Wh)[(size_t)c * 32 + lane];
        acc.x += w * v.x;
        acc.y += w * v.y;
        acc.z += w * v.z;
        acc.w += w * v.w;
    }
    ((float4*)out)[(size_t)warp * 32 + lane] = acc;
}

// ---------------- launch ----------------------------------------------------
extern "C" void kernel_launch(void* const* d_in, const int* in_sizes, int n_in,
                              void* d_out, int out_size) {
    const float* h = (const float*)d_in[0];
    const void*  ei = d_in[1];
    const float* W = (const float*)d_in[2];
    const float* a = (const float*)d_in[3];
    float* out = (float*)d_out;

    detect_kernel<<<1, 1>>>(ei);
    zero_kernel<<<100, 256>>>();
    gemm_kernel<<<(N_NODES + 31) / 32, 256>>>(h, W);
    score_kernel<<<(N_NODES + 7) / 8, 256>>>(a);
    edge1_kernel<<<(N_EDGES + 255) / 256, 256>>>(ei);
    scan_kernel<<<1, 1024>>>();
    edge2_kernel<<<(N_EDGES + 255) / 256, 256>>>(ei);
    agg_kernel<<<(N_NODES + 7) / 8, 256>>>(ei, out);
    (void)in_sizes; (void)n_in; (void)out_size;
}

// round 2
// speedup vs baseline: 1.2491x; 1.2491x over previous
#include <cuda_runtime.h>
#include <cstdint>

#define N_NODES 50000
#define N_FEAT  128
#define N_EDGES 800000
#define ALPHA   0.2f
#define EPS     1e-16f

// ---------------- scratch (device globals; no allocation allowed) ----------
__device__ float d_Wh[N_NODES * N_FEAT];      // 25.6 MB, L2-resident
__device__ float d_s1[N_NODES];
__device__ float d_s2[N_NODES];
__device__ int   d_counts[N_NODES];
__device__ int   d_starts[N_NODES + 1];
__device__ int   d_cursor[N_NODES];
__device__ int   d_col_sorted[N_EDGES];       // edge cols, grouped by dest row
__device__ float d_e_sorted[N_EDGES];         // leaky-relu scores, same order
__device__ int   g_is64;

// ---------------- edge-index dtype detection -------------------------------
// int32 ids read as u64 combine pairs -> high word is a node id -> huge value.
__global__ void detect_kernel(const void* ei) {
    if (threadIdx.x == 0 && blockIdx.x == 0) {
        const unsigned long long* p = (const unsigned long long*)ei;
        int big = 0;
        for (int i = 0; i < 64; i++)
            if (p[i] > (unsigned long long)N_NODES) big++;
        g_is64 = (big < 32) ? 1 : 0;
    }
}

__device__ __forceinline__ int edge_get(const void* ei, int which, int i, int is64) {
    if (is64) return (int)((const long long*)ei)[(size_t)which * N_EDGES + i];
    return ((const int*)ei)[which * N_EDGES + i];
}

// ---------------- zero counters --------------------------------------------
__global__ void zero_kernel() {
    int idx = blockIdx.x * blockDim.x + threadIdx.x;
    int stride = gridDim.x * blockDim.x;
    for (int i = idx; i < N_NODES; i += stride) {
        d_counts[i] = 0;
        d_cursor[i] = 0;
    }
}

// ---------------- GEMM: Wh = h @ W, fused s1/s2 epilogue -------------------
// 256 threads, 32-row tile. Thread (cg=t&31, rg=t>>5) owns a 4x4 tile:
// rows row0+rg*4+j, cols 4*cg..4*cg+3. A warp (fixed rg) spans all 128 cols
// of 4 rows -> shuffle-reduce gives s1/s2 for those rows for free.
__global__ void gemm_kernel(const float* __restrict__ h, const float* __restrict__ W,
                            const float* __restrict__ a) {
    __shared__ float hs[32 * N_FEAT];
    const int t = threadIdx.x;
    const int row0 = blockIdx.x * 32;

    for (int i = t; i < 32 * (N_FEAT / 4); i += 256) {
        int r = i >> 5;
        int c4 = i & 31;
        float4 v = make_float4(0.f, 0.f, 0.f, 0.f);
        int gr = row0 + r;
        if (gr < N_NODES) v = ((const float4*)h)[(size_t)gr * 32 + c4];
        ((float4*)hs)[i] = v;
    }
    __syncthreads();

    const int cg = t & 31;
    const int rg = t >> 5;
    float acc[4][4];
#pragma unroll
    for (int j = 0; j < 4; j++)
#pragma unroll
        for (int c = 0; c < 4; c++) acc[j][c] = 0.0f;

    const float4* Wv = (const float4*)W;
#pragma unroll 4
    for (int k = 0; k < N_FEAT; k++) {
        float4 w = __ldg(&Wv[k * 32 + cg]);
#pragma unroll
        for (int j = 0; j < 4; j++) {
            float hv = hs[(rg * 4 + j) * N_FEAT + k];
            acc[j][0] += hv * w.x;
            acc[j][1] += hv * w.y;
            acc[j][2] += hv * w.z;
            acc[j][3] += hv * w.w;
        }
    }

    // epilogue: write Wh + per-row s1/s2 partials -> warp reduce
    float4 a1 = __ldg(&((const float4*)a)[cg]);        // a[4cg..4cg+3]
    float4 a2 = __ldg(&((const float4*)a)[32 + cg]);   // a[128+4cg..]
#pragma unroll
    for (int j = 0; j < 4; j++) {
        int gr = row0 + rg * 4 + j;
        float s1 = acc[j][0] * a1.x + acc[j][1] * a1.y + acc[j][2] * a1.z + acc[j][3] * a1.w;
        float s2 = acc[j][0] * a2.x + acc[j][1] * a2.y + acc[j][2] * a2.z + acc[j][3] * a2.w;
#pragma unroll
        for (int off = 16; off > 0; off >>= 1) {
            s1 += __shfl_down_sync(0xffffffffu, s1, off);
            s2 += __shfl_down_sync(0xffffffffu, s2, off);
        }
        if (gr < N_NODES) {
            ((float4*)d_Wh)[(size_t)gr * 32 + cg] =
                make_float4(acc[j][0], acc[j][1], acc[j][2], acc[j][3]);
            if (cg == 0) { d_s1[gr] = s1; d_s2[gr] = s2; }
        }
    }
}

// ---------------- edge pass 1: degree histogram ----------------------------
__global__ void count_kernel(const void* __restrict__ ei) {
    int i = blockIdx.x * blockDim.x + threadIdx.x;
    if (i >= N_EDGES) return;
    int r = edge_get(ei, 0, i, g_is64);
    atomicAdd(&d_counts[r], 1);
}

// ---------------- single-block exclusive scan of counts --------------------
__global__ void scan_kernel() {
    __shared__ int sums[1024];
    const int t = threadIdx.x;
    const int CH = (N_NODES + 1023) / 1024;   // 49
    const int base = t * CH;
    int s = 0;
    for (int i = 0; i < CH; i++) {
        int idx = base + i;
        if (idx < N_NODES) s += d_counts[idx];
    }
    sums[t] = s;
    __syncthreads();
    for (int off = 1; off < 1024; off <<= 1) {
        int v = (t >= off) ? sums[t - off] : 0;
        __syncthreads();
        sums[t] += v;
        __syncthreads();
    }
    int run = (t == 0) ? 0 : sums[t - 1];
    for (int i = 0; i < CH; i++) {
        int idx = base + i;
        if (idx < N_NODES) {
            d_starts[idx] = run;
            run += d_counts[idx];
        }
    }
    if (t == 1023) d_starts[N_NODES] = sums[1023];
}

// ---------------- edge pass 2: score + counting-sort scatter ---------------
__global__ void scatter_kernel(const void* __restrict__ ei) {
    int i = blockIdx.x * blockDim.x + threadIdx.x;
    if (i >= N_EDGES) return;
    const int is64 = g_is64;
    int r = edge_get(ei, 0, i, is64);
    int c = edge_get(ei, 1, i, is64);
    float e = d_s1[r] + d_s2[c];
    e = (e > 0.0f) ? e : ALPHA * e;
    int pos = d_starts[r] + atomicAdd(&d_cursor[r], 1);
    d_col_sorted[pos] = c;
    d_e_sorted[pos] = e;
}

// ---------------- node kernel: softmax + aggregate, warp per node ----------
__global__ void node_kernel(float* __restrict__ out) {
    int warp = (blockIdx.x * blockDim.x + threadIdx.x) >> 5;
    int lane = threadIdx.x & 31;
    if (warp >= N_NODES) return;
    const int st = d_starts[warp];
    const int en = d_starts[warp + 1];

    // rowsum = sum(e) over segment (lane-strided, contiguous loads)
    float rs = 0.0f;
    for (int p = st + lane; p < en; p += 32) rs += d_e_sorted[p];
#pragma unroll
    for (int off = 16; off > 0; off >>= 1) rs += __shfl_xor_sync(0xffffffffu, rs, off);

    // expsum
    float es = 0.0f;
    for (int p = st + lane; p < en; p += 32) es += __expf(d_e_sorted[p] - rs);
#pragma unroll
    for (int off = 16; off > 0; off >>= 1) es += __shfl_xor_sync(0xffffffffu, es, off);
    const float inv = 1.0f / (es + EPS);

    // aggregate: serial over edges, lanes span the 128 features
    float4 acc = make_float4(0.f, 0.f, 0.f, 0.f);
    for (int p = st; p < en; p++) {
        int c = d_col_sorted[p];                       // broadcast load
        float w = __expf(d_e_sorted[p] - rs) * inv;    // broadcast load
        float4 v = ((const float4*)d_Wh)[(size_t)c * 32 + lane];
        acc.x += w * v.x;
        acc.y += w * v.y;
        acc.z += w * v.z;
        acc.w += w * v.w;
    }
    ((float4*)out)[(size_t)warp * 32 + lane] = acc;
}

// ---------------- launch ----------------------------------------------------
extern "C" void kernel_launch(void* const* d_in, const int* in_sizes, int n_in,
                              void* d_out, int out_size) {
    const float* h = (const float*)d_in[0];
    const void*  ei = d_in[1];
    const float* W = (const float*)d_in[2];
    const float* a = (const float*)d_in[3];
    float* out = (float*)d_out;

    detect_kernel<<<1, 1>>>(ei);
    zero_kernel<<<100, 256>>>();
    gemm_kernel<<<(N_NODES + 31) / 32, 256>>>(h, W, a);
    count_kernel<<<(N_EDGES + 255) / 256, 256>>>(ei);
    scan_kernel<<<1, 1024>>>();
    scatter_kernel<<<(N_EDGES + 255) / 256, 256>>>(ei);
    node_kernel<<<(N_NODES + 7) / 8, 256>>>(out);
    (void)in_sizes; (void)n_in; (void)out_size;
}

// round 4
// speedup vs baseline: 1.4672x; 1.1747x over previous
#include <cuda_runtime.h>
#include <cuda_bf16.h>
#include <cstdint>

#define N_NODES 50000
#define N_FEAT  128
#define N_EDGES 800000
#define ALPHA   0.2f
#define EPS     1e-16f

#define N_TILES   391              // ceil(50000/128)
#define M_PAD     (N_TILES * 128)  // 50048

// ---------------- scratch (device globals; zero-initialized) ----------------
__device__ float d_Wh[N_NODES * N_FEAT];                 // 25.6 MB
__device__ float d_s1[N_NODES];
__device__ float d_s2[N_NODES];
__device__ int   d_counts[N_NODES];
__device__ int   d_starts[N_NODES + 1];
__device__ int   d_cursor[N_NODES];
__device__ int   d_col_sorted[N_EDGES];
__device__ float d_e_sorted[N_EDGES];
// pre-swizzled bf16 tile images (row-local SW128 swizzle applied at prep time)
__device__ unsigned char d_Ahi[(size_t)M_PAD * 256];     // 12.8 MB
__device__ unsigned char d_Alo[(size_t)M_PAD * 256];     // 12.8 MB
__device__ unsigned char d_Bhi[32768];                   // Bt[n][k] two 16KB k-halves
__device__ unsigned char d_Blo[32768];
__device__ int   g_is64;

// ---------------- helpers ----------------------------------------------------
__device__ __forceinline__ unsigned swz(unsigned off) {   // SW128, row-local
    return off ^ ((off >> 3) & 0x70);
}
__device__ __forceinline__ uint32_t smem_u32(const void* p) {
    uint32_t a;
    asm("{ .reg .u64 t; cvta.to.shared.u64 t, %1; cvt.u32.u64 %0, t; }" : "=r"(a) : "l"(p));
    return a;
}
__device__ __forceinline__ void ldm_x4(uint32_t& r0, uint32_t& r1, uint32_t& r2, uint32_t& r3,
                                       uint32_t addr) {
    asm volatile("ldmatrix.sync.aligned.m8n8.x4.shared.b16 {%0,%1,%2,%3}, [%4];"
                 : "=r"(r0), "=r"(r1), "=r"(r2), "=r"(r3) : "r"(addr));
}
__device__ __forceinline__ void mma_bf16(float* c, uint32_t a0, uint32_t a1, uint32_t a2,
                                         uint32_t a3, uint32_t b0, uint32_t b1) {
    asm volatile(
        "mma.sync.aligned.m16n8k16.row.col.f32.bf16.bf16.f32 "
        "{%0,%1,%2,%3}, {%4,%5,%6,%7}, {%8,%9}, {%0,%1,%2,%3};"
        : "+f"(c[0]), "+f"(c[1]), "+f"(c[2]), "+f"(c[3])
        : "r"(a0), "r"(a1), "r"(a2), "r"(a3), "r"(b0), "r"(b1));
}
__device__ __forceinline__ unsigned short bfb(float x) {
    return __bfloat16_as_ushort(__float2bfloat16(x));
}
__device__ __forceinline__ float bff(unsigned short u) {
    return __bfloat162float(__ushort_as_bfloat16(u));
}
__device__ __forceinline__ int edge_get(const void* ei, int which, int i, int is64) {
    if (is64) return (int)((const long long*)ei)[(size_t)which * N_EDGES + i];
    return ((const int*)ei)[which * N_EDGES + i];
}

// ---------------- init: dtype detect + zero counters/accumulators -----------
__global__ void init_kernel(const void* ei) {
    int idx = blockIdx.x * blockDim.x + threadIdx.x;
    if (idx == 0) {
        const unsigned long long* p = (const unsigned long long*)ei;
        int big = 0;
        for (int i = 0; i < 64; i++)
            if (p[i] > (unsigned long long)N_NODES) big++;
        g_is64 = (big < 32) ? 1 : 0;
    }
    int stride = gridDim.x * blockDim.x;
    for (int i = idx; i < N_NODES; i += stride) {
        d_counts[i] = 0;
        d_cursor[i] = 0;
        d_s1[i] = 0.0f;
        d_s2[i] = 0.0f;
    }
}

// ---------------- prep B: Bt[n][k] = W[k][n], split hi/lo, swizzled ---------
__global__ void prepB_kernel(const float* __restrict__ W) {
    int idx = blockIdx.x * blockDim.x + threadIdx.x;   // 16384
    if (idx >= 16384) return;
    int k = idx >> 7, n = idx & 127;
    float x = W[k * 128 + n];
    unsigned short hi = bfb(x);
    unsigned short lo = bfb(x - bff(hi));
    unsigned off = swz((unsigned)((k >> 6) * 16384 + n * 128 + (k & 63) * 2));
    *(unsigned short*)(d_Bhi + off) = hi;
    *(unsigned short*)(d_Blo + off) = lo;
}

// ---------------- prep A: split h into hi/lo bf16 tile images ---------------
// thread -> (row m, 4 consecutive k). 50000*32 threads.
__global__ void prepA_kernel(const float* __restrict__ h) {
    int idx = blockIdx.x * blockDim.x + threadIdx.x;
    if (idx >= N_NODES * 32) return;
    int m = idx >> 5;
    int q = idx & 31;              // float4 index, k = q*4
    float4 v = ((const float4*)h)[(size_t)m * 32 + q];
    unsigned short h0 = bfb(v.x), h1 = bfb(v.y), h2 = bfb(v.z), h3 = bfb(v.w);
    unsigned short l0 = bfb(v.x - bff(h0)), l1 = bfb(v.y - bff(h1));
    unsigned short l2 = bfb(v.z - bff(h2)), l3 = bfb(v.w - bff(h3));
    int k = q * 4;
    unsigned off = (unsigned)((m >> 7) * 32768 + (k >> 6) * 16384 + (m & 127) * 128 + (k & 63) * 2);
    off = swz(off);   // 8B-aligned chunk preserved (xor bits 4-6)
    *(uint2*)(d_Ahi + off) = make_uint2((unsigned)h0 | ((unsigned)h1 << 16),
                                        (unsigned)h2 | ((unsigned)h3 << 16));
    *(uint2*)(d_Alo + off) = make_uint2((unsigned)l0 | ((unsigned)l1 << 16),
                                        (unsigned)l2 | ((unsigned)l3 << 16));
}

// ---------------- HMMA GEMM: Wh = h@W (split-bf16, K'=384), fused s1/s2 -----
// 256 thr = 8 warps (4x2). Block tile 128x128, warp tile 32x64.
__global__ void __launch_bounds__(256) gemm_mma_kernel(const float* __restrict__ a_vec) {
    __shared__ unsigned char sm[32768];        // A: [0,16K), B: [16K,32K)
    const int tid = threadIdx.x;
    const int wid = tid >> 5;
    const int lane = tid & 31;
    const int warpM = wid >> 1, warpN = wid & 1;
    const int m_base = warpM * 32, n_base = warpN * 64;
    const uint32_t sA = smem_u32(sm), sB = sA + 16384;
    const int m0g = blockIdx.x * 128;

    float c[2][8][4];
#pragma unroll
    for (int mi = 0; mi < 2; mi++)
#pragma unroll
        for (int ni = 0; ni < 8; ni++)
#pragma unroll
            for (int j = 0; j < 4; j++) c[mi][ni][j] = 0.0f;

    // per-thread ldmatrix address components (within-tile byte offsets, pre-swizzle)
    const unsigned arow = (unsigned)(lane & 15);
    const unsigned acol16 = (unsigned)((lane >> 4) * 16);
    const unsigned brow = (unsigned)((lane & 7) + ((lane >> 4) << 3));
    const unsigned bcol16 = (unsigned)(((lane >> 3) & 1) * 16);

#pragma unroll 1
    for (int kc = 0; kc < 6; kc++) {
        const unsigned char* Asrc = ((kc < 4) ? d_Ahi : d_Alo)
                                    + (size_t)blockIdx.x * 32768 + (kc & 1) * 16384;
        const unsigned char* Bsrc = ((kc == 2 || kc == 3) ? d_Blo : d_Bhi) + (kc & 1) * 16384;
        __syncthreads();
#pragma unroll
        for (int i = 0; i < 4; i++) {
            ((uint4*)sm)[tid + i * 256] = ((const uint4*)Asrc)[tid + i * 256];
            ((uint4*)(sm + 16384))[tid + i * 256] = ((const uint4*)Bsrc)[tid + i * 256];
        }
        __syncthreads();

#pragma unroll
        for (int ks = 0; ks < 4; ks++) {
            const unsigned kb = (unsigned)(ks * 32);
            uint32_t a[2][4];
#pragma unroll
            for (int mi = 0; mi < 2; mi++) {
                unsigned off = (unsigned)(m_base + mi * 16 + arow) * 128 + kb + acol16;
                ldm_x4(a[mi][0], a[mi][1], a[mi][2], a[mi][3], sA + swz(off));
            }
            uint32_t b[8][2];
#pragma unroll
            for (int ng = 0; ng < 4; ng++) {
                unsigned off = (unsigned)(n_base + ng * 16 + brow) * 128 + kb + bcol16;
                uint32_t r0, r1, r2, r3;
                ldm_x4(r0, r1, r2, r3, sB + swz(off));
                b[ng * 2][0] = r0; b[ng * 2][1] = r1;
                b[ng * 2 + 1][0] = r2; b[ng * 2 + 1][1] = r3;
            }
#pragma unroll
            for (int mi = 0; mi < 2; mi++)
#pragma unroll
                for (int ni = 0; ni < 8; ni++)
                    mma_bf16(c[mi][ni], a[mi][0], a[mi][1], a[mi][2], a[mi][3],
                             b[ni][0], b[ni][1]);
        }
    }

    // epilogue: write Wh, fused s1/s2 (quad reduce + atomic)
    const int tig = lane & 3, g = lane >> 2;
#pragma unroll
    for (int mi = 0; mi < 2; mi++) {
#pragma unroll
        for (int half = 0; half < 2; half++) {
            int gr = m0g + m_base + mi * 16 + g + half * 8;
            float s1 = 0.0f, s2 = 0.0f;
#pragma unroll
            for (int ni = 0; ni < 8; ni++) {
                float v0 = c[mi][ni][half * 2 + 0];
                float v1 = c[mi][ni][half * 2 + 1];
                int col = n_base + ni * 8 + tig * 2;
                s1 += v0 * __ldg(&a_vec[col]) + v1 * __ldg(&a_vec[col + 1]);
                s2 += v0 * __ldg(&a_vec[128 + col]) + v1 * __ldg(&a_vec[128 + col + 1]);
                if (gr < N_NODES)
                    *(float2*)&d_Wh[(size_t)gr * 128 + col] = make_float2(v0, v1);
            }
            s1 += __shfl_xor_sync(0xffffffffu, s1, 1);
            s1 += __shfl_xor_sync(0xffffffffu, s1, 2);
            s2 += __shfl_xor_sync(0xffffffffu, s2, 1);
            s2 += __shfl_xor_sync(0xffffffffu, s2, 2);
            if (tig == 0 && gr < N_NODES) {
                atomicAdd(&d_s1[gr], s1);
                atomicAdd(&d_s2[gr], s2);
            }
        }
    }
}

// ---------------- degree histogram, 4 edges/thread ---------------------------
__global__ void count_kernel(const void* __restrict__ ei) {
    int t = blockIdx.x * blockDim.x + threadIdx.x;
    int base = t * 4;
    if (base >= N_EDGES) return;
    if (g_is64) {
        longlong2 p0 = ((const longlong2*)ei)[base >> 1];
        longlong2 p1 = ((const longlong2*)ei)[(base >> 1) + 1];
        atomicAdd(&d_counts[(int)p0.x], 1);
        atomicAdd(&d_counts[(int)p0.y], 1);
        atomicAdd(&d_counts[(int)p1.x], 1);
        atomicAdd(&d_counts[(int)p1.y], 1);
    } else {
        int4 q = ((const int4*)ei)[base >> 2];
        atomicAdd(&d_counts[q.x], 1);
        atomicAdd(&d_counts[q.y], 1);
        atomicAdd(&d_counts[q.z], 1);
        atomicAdd(&d_counts[q.w], 1);
    }
}

// ---------------- single-block exclusive scan --------------------------------
__global__ void scan_kernel() {
    __shared__ int sums[1024];
    const int t = threadIdx.x;
    const int CH = (N_NODES + 1023) / 1024;
    const int base = t * CH;
    int s = 0;
    for (int i = 0; i < CH; i++) {
        int idx = base + i;
        if (idx < N_NODES) s += d_counts[idx];
    }
    sums[t] = s;
    __syncthreads();
    for (int off = 1; off < 1024; off <<= 1) {
        int v = (t >= off) ? sums[t - off] : 0;
        __syncthreads();
        sums[t] += v;
        __syncthreads();
    }
    int run = (t == 0) ? 0 : sums[t - 1];
    for (int i = 0; i < CH; i++) {
        int idx = base + i;
        if (idx < N_NODES) {
            d_starts[idx] = run;
            run += d_counts[idx];
        }
    }
    if (t == 1023) d_starts[N_NODES] = sums[1023];
}

// ---------------- score + counting-sort scatter, 2 edges/thread --------------
__global__ void scatter_kernel(const void* __restrict__ ei) {
    int t = blockIdx.x * blockDim.x + threadIdx.x;
    int i = t * 2;
    if (i >= N_EDGES) return;
    int r0, r1, c0, c1;
    if (g_is64) {
        longlong2 rr = ((const longlong2*)ei)[i >> 1];
        longlong2 cc = ((const longlong2*)ei)[(N_EDGES >> 1) + (i >> 1)];
        r0 = (int)rr.x; r1 = (int)rr.y; c0 = (int)cc.x; c1 = (int)cc.y;
    } else {
        int2 rr = ((const int2*)ei)[i >> 1];
        int2 cc = ((const int2*)ei)[(N_EDGES >> 1) + (i >> 1)];
        r0 = rr.x; r1 = rr.y; c0 = cc.x; c1 = cc.y;
    }
    float e0 = d_s1[r0] + d_s2[c0];
    float e1 = d_s1[r1] + d_s2[c1];
    e0 = (e0 > 0.0f) ? e0 : ALPHA * e0;
    e1 = (e1 > 0.0f) ? e1 : ALPHA * e1;
    int p0 = d_starts[r0] + atomicAdd(&d_cursor[r0], 1);
    d_col_sorted[p0] = c0;
    d_e_sorted[p0] = e0;
    int p1 = d_starts[r1] + atomicAdd(&d_cursor[r1], 1);
    d_col_sorted[p1] = c1;
    d_e_sorted[p1] = e1;
}

// ---------------- node: softmax + aggregate, warp per node, MLP 4 -----------
__global__ void node_kernel(float* __restrict__ out) {
    int warp = (blockIdx.x * blockDim.x + threadIdx.x) >> 5;
    int lane = threadIdx.x & 31;
    if (warp >= N_NODES) return;
    const int st = d_starts[warp];
    const int en = d_starts[warp + 1];

    float rs = 0.0f;
    for (int p = st + lane; p < en; p += 32) rs += d_e_sorted[p];
#pragma unroll
    for (int off = 16; off > 0; off >>= 1) rs += __shfl_xor_sync(0xffffffffu, rs, off);

    float es = 0.0f;
    for (int p = st + lane; p < en; p += 32) es += __expf(d_e_sorted[p] - rs);
#pragma unroll
    for (int off = 16; off > 0; off >>= 1) es += __shfl_xor_sync(0xffffffffu, es, off);
    const float inv = 1.0f / (es + EPS);

    float4 acc = make_float4(0.f, 0.f, 0.f, 0.f);
    int p = st;
    for (; p + 4 <= en; p += 4) {
        int c0 = d_col_sorted[p], c1 = d_col_sorted[p + 1];
        int c2 = d_col_sorted[p + 2], c3 = d_col_sorted[p + 3];
        float w0 = __expf(d_e_sorted[p] - rs) * inv;
        float w1 = __expf(d_e_sorted[p + 1] - rs) * inv;
        float w2 = __expf(d_e_sorted[p + 2] - rs) * inv;
        float w3 = __expf(d_e_sorted[p + 3] - rs) * inv;
        float4 v0 = ((const float4*)d_Wh)[(size_t)c0 * 32 + lane];
        float4 v1 = ((const float4*)d_Wh)[(size_t)c1 * 32 + lane];
        float4 v2 = ((const float4*)d_Wh)[(size_t)c2 * 32 + lane];
        float4 v3 = ((const float4*)d_Wh)[(size_t)c3 * 32 + lane];
        acc.x += w0 * v0.x + w1 * v1.x + w2 * v2.x + w3 * v3.x;
        acc.y += w0 * v0.y + w1 * v1.y + w2 * v2.y + w3 * v3.y;
        acc.z += w0 * v0.z + w1 * v1.z + w2 * v2.z + w3 * v3.z;
        acc.w += w0 * v0.w + w1 * v1.w + w2 * v2.w + w3 * v3.w;
    }
    for (; p < en; p++) {
        int cc = d_col_sorted[p];
        float w = __expf(d_e_sorted[p] - rs) * inv;
        float4 v = ((const float4*)d_Wh)[(size_t)cc * 32 + lane];
        acc.x += w * v.x;
        acc.y += w * v.y;
        acc.z += w * v.z;
        acc.w += w * v.w;
    }
    ((float4*)out)[(size_t)warp * 32 + lane] = acc;
}

// ---------------- launch -----------------------------------------------------
extern "C" void kernel_launch(void* const* d_in, const int* in_sizes, int n_in,
                              void* d_out, int out_size) {
    const float* h = (const float*)d_in[0];
    const void*  ei = d_in[1];
    const float* W = (const float*)d_in[2];
    const float* a = (const float*)d_in[3];
    float* out = (float*)d_out;

    init_kernel<<<98, 512>>>(ei);
    prepB_kernel<<<64, 256>>>(W);
    prepA_kernel<<<(N_NODES * 32 + 255) / 256, 256>>>(h);
    gemm_mma_kernel<<<N_TILES, 256>>>(a);
    count_kernel<<<(N_EDGES / 4 + 255) / 256, 256>>>(ei);
    scan_kernel<<<1, 1024>>>();
    scatter_kernel<<<(N_EDGES / 2 + 255) / 256, 256>>>(ei);
    node_kernel<<<(N_NODES + 7) / 8, 256>>>(out);
    (void)in_sizes; (void)n_in; (void)out_size;
}

// round 5
// speedup vs baseline: 1.5476x; 1.0548x over previous
#include <cuda_runtime.h>
#include <cuda_bf16.h>
#include <cuda_fp16.h>
#include <cstdint>

#define N_NODES 50000
#define N_FEAT  128
#define N_EDGES 800000
#define ALPHA   0.2f
#define EPS     1e-16f

#define N_TILES   391              // ceil(50000/128)

// ---------------- scratch (device globals) ----------------------------------
__device__ __half d_Wh16[(size_t)N_NODES * N_FEAT];      // 12.8 MB, gather source
__device__ float d_s1[N_NODES];
__device__ float d_s2[N_NODES];
__device__ int   d_counts[N_NODES];
__device__ int   d_starts[N_NODES + 1];
__device__ int   d_cursor[N_NODES];
__device__ int   d_col_sorted[N_EDGES];
__device__ float d_e_sorted[N_EDGES];
__device__ unsigned char d_Bhi[32768];                   // pre-swizzled bf16 W^T images
__device__ unsigned char d_Blo[32768];
__device__ int   g_is64;

// ---------------- helpers ----------------------------------------------------
__device__ __forceinline__ unsigned swz(unsigned off) {   // SW128, row-local
    return off ^ ((off >> 3) & 0x70);
}
__device__ __forceinline__ uint32_t smem_u32(const void* p) {
    uint32_t a;
    asm("{ .reg .u64 t; cvta.to.shared.u64 t, %1; cvt.u32.u64 %0, t; }" : "=r"(a) : "l"(p));
    return a;
}
__device__ __forceinline__ void ldm_x4(uint32_t& r0, uint32_t& r1, uint32_t& r2, uint32_t& r3,
                                       uint32_t addr) {
    asm volatile("ldmatrix.sync.aligned.m8n8.x4.shared.b16 {%0,%1,%2,%3}, [%4];"
                 : "=r"(r0), "=r"(r1), "=r"(r2), "=r"(r3) : "r"(addr));
}
__device__ __forceinline__ void mma_bf16(float* c, uint32_t a0, uint32_t a1, uint32_t a2,
                                         uint32_t a3, uint32_t b0, uint32_t b1) {
    asm volatile(
        "mma.sync.aligned.m16n8k16.row.col.f32.bf16.bf16.f32 "
        "{%0,%1,%2,%3}, {%4,%5,%6,%7}, {%8,%9}, {%0,%1,%2,%3};"
        : "+f"(c[0]), "+f"(c[1]), "+f"(c[2]), "+f"(c[3])
        : "r"(a0), "r"(a1), "r"(a2), "r"(a3), "r"(b0), "r"(b1));
}
__device__ __forceinline__ unsigned short bfb(float x) {
    return __bfloat16_as_ushort(__float2bfloat16(x));
}
__device__ __forceinline__ float bff(unsigned short u) {
    return __bfloat162float(__ushort_as_bfloat16(u));
}

// ---------------- init: dtype detect + zero counters/accumulators -----------
__global__ void init_kernel(const void* ei) {
    int idx = blockIdx.x * blockDim.x + threadIdx.x;
    if (idx == 0) {
        const unsigned long long* p = (const unsigned long long*)ei;
        int big = 0;
        for (int i = 0; i < 64; i++)
            if (p[i] > (unsigned long long)N_NODES) big++;
        g_is64 = (big < 32) ? 1 : 0;
    }
    int stride = gridDim.x * blockDim.x;
    for (int i = idx; i < N_NODES; i += stride) {
        d_counts[i] = 0;
        d_cursor[i] = 0;
        d_s1[i] = 0.0f;
        d_s2[i] = 0.0f;
    }
}

// ---------------- prep B: Bt[n][k] = W[k][n], split hi/lo, swizzled ---------
__global__ void prepB_kernel(const float* __restrict__ W) {
    int idx = blockIdx.x * blockDim.x + threadIdx.x;   // 16384
    if (idx >= 16384) return;
    int k = idx >> 7, n = idx & 127;
    float x = W[k * 128 + n];
    unsigned short hi = bfb(x);
    unsigned short lo = bfb(x - bff(hi));
    unsigned off = swz((unsigned)((k >> 6) * 16384 + n * 128 + (k & 63) * 2));
    *(unsigned short*)(d_Bhi + off) = hi;
    *(unsigned short*)(d_Blo + off) = lo;
}

// ---------------- HMMA GEMM: Wh = h@W, A-split fused, fused s1/s2 -----------
// 256 thr = 8 warps (4x2). Block tile 128x128, warp tile 32x64.
// smem: AHI[0,32K) ALO[32K,64K) BHI[64K,96K) BLO[96K,128K)
#define SM_AHI 0
#define SM_ALO 32768
#define SM_BHI 65536
#define SM_BLO 98304
#define SM_TOT 131072

__global__ void __launch_bounds__(256) gemm_mma_kernel(const float* __restrict__ h,
                                                       const float* __restrict__ a_vec) {
    extern __shared__ unsigned char sm[];
    const int tid = threadIdx.x;
    const int wid = tid >> 5;
    const int lane = tid & 31;
    const int warpM = wid >> 1, warpN = wid & 1;
    const int m_base = warpM * 32, n_base = warpN * 64;
    const uint32_t sbase = smem_u32(sm);
    const int m0g = blockIdx.x * 128;

    // copy pre-swizzled B images (linear copy preserves layout): 64KB
#pragma unroll
    for (int i = 0; i < 8; i++) {
        ((uint4*)(sm + SM_BHI))[tid + i * 256] = ((const uint4*)d_Bhi)[tid + i * 256];
        ((uint4*)(sm + SM_BLO))[tid + i * 256] = ((const uint4*)d_Blo)[tid + i * 256];
    }

    // load h fp32 tile -> split -> swizzled bf16 hi/lo smem images
#pragma unroll
    for (int j = 0; j < 16; j++) {
        int i = tid + j * 256;                 // 0..4095
        int row = i >> 5, q = i & 31;          // q = float4 index, k = q*4
        int gr = m0g + row;
        float4 v = make_float4(0.f, 0.f, 0.f, 0.f);
        if (gr < N_NODES) v = ((const float4*)h)[(size_t)gr * 32 + q];
        unsigned short h0 = bfb(v.x), h1 = bfb(v.y), h2 = bfb(v.z), h3 = bfb(v.w);
        unsigned short l0 = bfb(v.x - bff(h0)), l1 = bfb(v.y - bff(h1));
        unsigned short l2 = bfb(v.z - bff(h2)), l3 = bfb(v.w - bff(h3));
        int k = q * 4;
        unsigned off = swz((unsigned)((k >> 6) * 16384 + row * 128 + (k & 63) * 2));
        *(uint2*)(sm + SM_AHI + off) = make_uint2((unsigned)h0 | ((unsigned)h1 << 16),
                                                  (unsigned)h2 | ((unsigned)h3 << 16));
        *(uint2*)(sm + SM_ALO + off) = make_uint2((unsigned)l0 | ((unsigned)l1 << 16),
                                                  (unsigned)l2 | ((unsigned)l3 << 16));
    }
    __syncthreads();

    float c[2][8][4];
#pragma unroll
    for (int mi = 0; mi < 2; mi++)
#pragma unroll
        for (int ni = 0; ni < 8; ni++)
#pragma unroll
            for (int j = 0; j < 4; j++) c[mi][ni][j] = 0.0f;

    const unsigned arow = (unsigned)(lane & 15);
    const unsigned acol16 = (unsigned)((lane >> 4) * 16);
    const unsigned brow = (unsigned)((lane & 7) + ((lane >> 4) << 3));
    const unsigned bcol16 = (unsigned)(((lane >> 3) & 1) * 16);

    // mainloop: 3 terms (hi*hi, hi*lo, lo*hi) x 2 k-halves x 4 k-steps, all smem
#pragma unroll 1
    for (int t3 = 0; t3 < 3; t3++) {
        const uint32_t sA = sbase + ((t3 == 2) ? SM_ALO : SM_AHI);
        const uint32_t sB = sbase + ((t3 == 1) ? SM_BLO : SM_BHI);
#pragma unroll
        for (int kh = 0; kh < 2; kh++) {
#pragma unroll
            for (int ks = 0; ks < 4; ks++) {
                const unsigned kb = (unsigned)(kh * 16384 + ks * 32);
                uint32_t a[2][4];
#pragma unroll
                for (int mi = 0; mi < 2; mi++) {
                    unsigned off = (unsigned)(m_base + mi * 16 + arow) * 128 + ks * 32 + acol16;
                    ldm_x4(a[mi][0], a[mi][1], a[mi][2], a[mi][3], sA + kh * 16384 + swz(off));
                }
                uint32_t b[8][2];
#pragma unroll
                for (int ng = 0; ng < 4; ng++) {
                    unsigned off = (unsigned)(n_base + ng * 16 + brow) * 128 + ks * 32 + bcol16;
                    uint32_t r0, r1, r2, r3;
                    ldm_x4(r0, r1, r2, r3, sB + kh * 16384 + swz(off));
                    b[ng * 2][0] = r0; b[ng * 2][1] = r1;
                    b[ng * 2 + 1][0] = r2; b[ng * 2 + 1][1] = r3;
                }
#pragma unroll
                for (int mi = 0; mi < 2; mi++)
#pragma unroll
                    for (int ni = 0; ni < 8; ni++)
                        mma_bf16(c[mi][ni], a[mi][0], a[mi][1], a[mi][2], a[mi][3],
                                 b[ni][0], b[ni][1]);
                (void)kb;
            }
        }
    }

    // epilogue: fp16 Wh + fused s1/s2 (quad reduce + atomic)
    const int tig = lane & 3, g = lane >> 2;
#pragma unroll
    for (int mi = 0; mi < 2; mi++) {
#pragma unroll
        for (int half = 0; half < 2; half++) {
            int gr = m0g + m_base + mi * 16 + g + half * 8;
            float s1 = 0.0f, s2 = 0.0f;
#pragma unroll
            for (int ni = 0; ni < 8; ni++) {
                float v0 = c[mi][ni][half * 2 + 0];
                float v1 = c[mi][ni][half * 2 + 1];
                int col = n_base + ni * 8 + tig * 2;
                s1 += v0 * __ldg(&a_vec[col]) + v1 * __ldg(&a_vec[col + 1]);
                s2 += v0 * __ldg(&a_vec[128 + col]) + v1 * __ldg(&a_vec[128 + col + 1]);
                if (gr < N_NODES)
                    *(__half2*)&d_Wh16[(size_t)gr * 128 + col] = __floats2half2_rn(v0, v1);
            }
            s1 += __shfl_xor_sync(0xffffffffu, s1, 1);
            s1 += __shfl_xor_sync(0xffffffffu, s1, 2);
            s2 += __shfl_xor_sync(0xffffffffu, s2, 1);
            s2 += __shfl_xor_sync(0xffffffffu, s2, 2);
            if (tig == 0 && gr < N_NODES) {
                atomicAdd(&d_s1[gr], s1);
                atomicAdd(&d_s2[gr], s2);
            }
        }
    }
}

// ---------------- degree histogram, 4 edges/thread ---------------------------
__global__ void count_kernel(const void* __restrict__ ei) {
    int t = blockIdx.x * blockDim.x + threadIdx.x;
    int base = t * 4;
    if (base >= N_EDGES) return;
    if (g_is64) {
        longlong2 p0 = ((const longlong2*)ei)[base >> 1];
        longlong2 p1 = ((const longlong2*)ei)[(base >> 1) + 1];
        atomicAdd(&d_counts[(int)p0.x], 1);
        atomicAdd(&d_counts[(int)p0.y], 1);
        atomicAdd(&d_counts[(int)p1.x], 1);
        atomicAdd(&d_counts[(int)p1.y], 1);
    } else {
        int4 q = ((const int4*)ei)[base >> 2];
        atomicAdd(&d_counts[q.x], 1);
        atomicAdd(&d_counts[q.y], 1);
        atomicAdd(&d_counts[q.z], 1);
        atomicAdd(&d_counts[q.w], 1);
    }
}

// ---------------- single-block exclusive scan --------------------------------
__global__ void scan_kernel() {
    __shared__ int sums[1024];
    const int t = threadIdx.x;
    const int CH = (N_NODES + 1023) / 1024;
    const int base = t * CH;
    int s = 0;
    for (int i = 0; i < CH; i++) {
        int idx = base + i;
        if (idx < N_NODES) s += d_counts[idx];
    }
    sums[t] = s;
    __syncthreads();
    for (int off = 1; off < 1024; off <<= 1) {
        int v = (t >= off) ? sums[t - off] : 0;
        __syncthreads();
        sums[t] += v;
        __syncthreads();
    }
    int run = (t == 0) ? 0 : sums[t - 1];
    for (int i = 0; i < CH; i++) {
        int idx = base + i;
        if (idx < N_NODES) {
            d_starts[idx] = run;
            run += d_counts[idx];
        }
    }
    if (t == 1023) d_starts[N_NODES] = sums[1023];
}

// ---------------- score + counting-sort scatter, 4 edges/thread --------------
__global__ void scatter_kernel(const void* __restrict__ ei) {
    int t = blockIdx.x * blockDim.x + threadIdx.x;
    int i = t * 4;
    if (i >= N_EDGES) return;
    int r[4], c[4];
    if (g_is64) {
        longlong2 r0 = ((const longlong2*)ei)[i >> 1];
        longlong2 r1 = ((const longlong2*)ei)[(i >> 1) + 1];
        longlong2 c0 = ((const longlong2*)ei)[(N_EDGES >> 1) + (i >> 1)];
        longlong2 c1 = ((const longlong2*)ei)[(N_EDGES >> 1) + (i >> 1) + 1];
        r[0] = (int)r0.x; r[1] = (int)r0.y; r[2] = (int)r1.x; r[3] = (int)r1.y;
        c[0] = (int)c0.x; c[1] = (int)c0.y; c[2] = (int)c1.x; c[3] = (int)c1.y;
    } else {
        int4 rr = ((const int4*)ei)[i >> 2];
        int4 cc = ((const int4*)ei)[(N_EDGES >> 2) + (i >> 2)];
        r[0] = rr.x; r[1] = rr.y; r[2] = rr.z; r[3] = rr.w;
        c[0] = cc.x; c[1] = cc.y; c[2] = cc.z; c[3] = cc.w;
    }
#pragma unroll
    for (int j = 0; j < 4; j++) {
        float e = d_s1[r[j]] + d_s2[c[j]];
        e = (e > 0.0f) ? e : ALPHA * e;
        int p = d_starts[r[j]] + atomicAdd(&d_cursor[r[j]], 1);
        d_col_sorted[p] = c[j];
        d_e_sorted[p] = e;
    }
}

// ---------------- node: softmax + fp16 aggregate, warp per node -------------
__global__ void node_kernel(float* __restrict__ out) {
    int warp = (blockIdx.x * blockDim.x + threadIdx.x) >> 5;
    int lane = threadIdx.x & 31;
    if (warp >= N_NODES) return;
    const int st = d_starts[warp];
    const int en = d_starts[warp + 1];

    float rs = 0.0f;
    for (int p = st + lane; p < en; p += 32) rs += d_e_sorted[p];
#pragma unroll
    for (int off = 16; off > 0; off >>= 1) rs += __shfl_xor_sync(0xffffffffu, rs, off);

    float es = 0.0f;
    for (int p = st + lane; p < en; p += 32) es += __expf(d_e_sorted[p] - rs);
#pragma unroll
    for (int off = 16; off > 0; off >>= 1) es += __shfl_xor_sync(0xffffffffu, es, off);
    const float inv = 1.0f / (es + EPS);

    const uint2* Wv = (const uint2*)d_Wh16;   // row = 32 uint2 (4 halves each)
    float ax = 0.f, ay = 0.f, az = 0.f, aw = 0.f;
    int p = st;
    for (; p + 4 <= en; p += 4) {
        int c0 = d_col_sorted[p], c1 = d_col_sorted[p + 1];
        int c2 = d_col_sorted[p + 2], c3 = d_col_sorted[p + 3];
        float w0 = __expf(d_e_sorted[p] - rs) * inv;
        float w1 = __expf(d_e_sorted[p + 1] - rs) * inv;
        float w2 = __expf(d_e_sorted[p + 2] - rs) * inv;
        float w3 = __expf(d_e_sorted[p + 3] - rs) * inv;
        uint2 u0 = Wv[(size_t)c0 * 32 + lane];
        uint2 u1 = Wv[(size_t)c1 * 32 + lane];
        uint2 u2 = Wv[(size_t)c2 * 32 + lane];
        uint2 u3 = Wv[(size_t)c3 * 32 + lane];
        float2 p0a = __half22float2(*(__half2*)&u0.x), p0b = __half22float2(*(__half2*)&u0.y);
        float2 p1a = __half22float2(*(__half2*)&u1.x), p1b = __half22float2(*(__half2*)&u1.y);
        float2 p2a = __half22float2(*(__half2*)&u2.x), p2b = __half22float2(*(__half2*)&u2.y);
        float2 p3a = __half22float2(*(__half2*)&u3.x), p3b = __half22float2(*(__half2*)&u3.y);
        ax += w0 * p0a.x + w1 * p1a.x + w2 * p2a.x + w3 * p3a.x;
        ay += w0 * p0a.y + w1 * p1a.y + w2 * p2a.y + w3 * p3a.y;
        az += w0 * p0b.x + w1 * p1b.x + w2 * p2b.x + w3 * p3b.x;
        aw += w0 * p0b.y + w1 * p1b.y + w2 * p2b.y + w3 * p3b.y;
    }
    for (; p < en; p++) {
        int cc = d_col_sorted[p];
        float w = __expf(d_e_sorted[p] - rs) * inv;
        uint2 u = Wv[(size_t)cc * 32 + lane];
        float2 pa = __half22float2(*(__half2*)&u.x), pb = __half22float2(*(__half2*)&u.y);
        ax += w * pa.x; ay += w * pa.y; az += w * pb.x; aw += w * pb.y;
    }
    ((float4*)out)[(size_t)warp * 32 + lane] = make_float4(ax, ay, az, aw);
}

// ---------------- launch -----------------------------------------------------
extern "C" void kernel_launch(void* const* d_in, const int* in_sizes, int n_in,
                              void* d_out, int out_size) {
    const float* h = (const float*)d_in[0];
    const void*  ei = d_in[1];
    const float* W = (const float*)d_in[2];
    const float* a = (const float*)d_in[3];
    float* out = (float*)d_out;

    cudaFuncSetAttribute(gemm_mma_kernel, cudaFuncAttributeMaxDynamicSharedMemorySize, SM_TOT);

    init_kernel<<<98, 512>>>(ei);
    prepB_kernel<<<64, 256>>>(W);
    gemm_mma_kernel<<<N_TILES, 256, SM_TOT>>>(h, a);
    count_kernel<<<(N_EDGES / 4 + 255) / 256, 256>>>(ei);
    scan_kernel<<<1, 1024>>>();
    scatter_kernel<<<(N_EDGES / 4 + 255) / 256, 256>>>(ei);
    node_kernel<<<(N_NODES + 7) / 8, 256>>>(out);
    (void)in_sizes; (void)n_in; (void)out_size;
}